// round 6
// baseline (speedup 1.0000x reference)
#include <cuda_runtime.h>
#include <cuda_bf16.h>
#include <cstdint>

// Problem shape (fixed by dataset): N=2,000,000 atoms, D=64, HID=32, H=3, G=50,000
#define D_DIM   64
#define HID_DIM 32
#define H_DIM   3

#define MAX_N 2000000
#define MAX_G 50000
#define SEG_CAP 128

typedef unsigned long long ull;

// Scratch (device globals)
__device__ float g_scores[(size_t)MAX_N * H_DIM];   // only used by rare big-segment path
__device__ int   g_segstart[MAX_G + 1];

// ---------------- packed fp32x2 helpers ----------------
__device__ __forceinline__ ull pack2(float v) {
    ull r; asm("mov.b64 %0, {%1, %1};" : "=l"(r) : "f"(v)); return r;
}
__device__ __forceinline__ ull fma2(ull a, ull b, ull c) {
    ull d; asm("fma.rn.f32x2 %0, %1, %2, %3;" : "=l"(d) : "l"(a), "l"(b), "l"(c)); return d;
}
__device__ __forceinline__ void unpack2(ull v, float& lo, float& hi) {
    asm("mov.b64 {%0, %1}, %2;" : "=f"(lo), "=f"(hi) : "l"(v));
}

// ---------------- bf16 helpers ----------------
__device__ __forceinline__ uint32_t pk2bf(float a, float b) {
    __nv_bfloat162 h = __floats2bfloat162_rn(a, b);
    return *reinterpret_cast<uint32_t*>(&h);
}
__device__ __forceinline__ float bfhi(float x) {
    return __bfloat162float(__float2bfloat16_rn(x));
}

// warp-level tensor-core MMA (sm_80+ feature set; compiles for plain sm_103)
__device__ __forceinline__ void mma16816(float c[4],
    uint32_t a0, uint32_t a1, uint32_t a2, uint32_t a3,
    uint32_t b0, uint32_t b1)
{
    asm volatile(
        "mma.sync.aligned.m16n8k16.row.col.f32.bf16.bf16.f32 "
        "{%0,%1,%2,%3}, {%4,%5,%6,%7}, {%8,%9}, {%0,%1,%2,%3};"
        : "+f"(c[0]), "+f"(c[1]), "+f"(c[2]), "+f"(c[3])
        : "r"(a0), "r"(a1), "r"(a2), "r"(a3), "r"(b0), "r"(b1));
}

// ---------------------------------------------------------------------------
// Kernel 1: segment boundaries from sorted owner array.
// ---------------------------------------------------------------------------
__global__ void k_bounds(const int* __restrict__ owner, int N, int G)
{
    int i = blockIdx.x * blockDim.x + threadIdx.x;
    if (i >= N) return;
    int o = owner[i];
    if (i == 0) {
        for (int g = 0; g <= o; ++g) g_segstart[g] = 0;
    } else {
        int po = owner[i - 1];
        for (int g = po + 1; g <= o; ++g) g_segstart[g] = i;
    }
    if (i == N - 1) {
        for (int g = o + 1; g <= G; ++g) g_segstart[g] = N;
    }
}

// ---------------------------------------------------------------------------
// Kernel 2 (FUSED): one persistent warp per segment.
//   Phase A: segment scores via 3-term double-bf16 mma.sync -> per-warp smem
//   Phase B: warp-shuffle softmax (scores -> attn weights, in smem)
//   Phase C: weighted pooling, re-reading the segment's X rows (L1-hot)
// X is streamed from DRAM exactly once.
// ---------------------------------------------------------------------------
__global__ __launch_bounds__(128) void k_fused(
    const float* __restrict__ X,
    const float* __restrict__ w1, const float* __restrict__ b1,
    const float* __restrict__ w2, const float* __restrict__ b2,
    float* __restrict__ out, int N, int G)
{
    __shared__ float swbuf[4][SEG_CAP * H_DIM];

    const int lane = threadIdx.x & 31;
    const int wid  = threadIdx.x >> 5;
    const int g    = lane >> 2;   // row group 0..7
    const int tig  = lane & 3;    // thread-in-group

    // ---- B fragments (w1, hi/lo) in registers ----
    uint32_t bh[4][4][2], bl[4][4][2];
#pragma unroll
    for (int t = 0; t < 4; ++t) {
        const int col = g + 8 * t;
#pragma unroll
        for (int s = 0; s < 4; ++s) {
            const int k0 = tig * 2 + 16 * s;
            float w00 = __ldg(&w1[(k0 + 0) * HID_DIM + col]);
            float w01 = __ldg(&w1[(k0 + 1) * HID_DIM + col]);
            float w08 = __ldg(&w1[(k0 + 8) * HID_DIM + col]);
            float w09 = __ldg(&w1[(k0 + 9) * HID_DIM + col]);
            bh[t][s][0] = pk2bf(w00, w01);
            bh[t][s][1] = pk2bf(w08, w09);
            bl[t][s][0] = pk2bf(w00 - bfhi(w00), w01 - bfhi(w01));
            bl[t][s][1] = pk2bf(w08 - bfhi(w08), w09 - bfhi(w09));
        }
    }

    // ---- epilogue constants ----
    float b1v[4][2], w2v[4][2][3];
#pragma unroll
    for (int t = 0; t < 4; ++t)
#pragma unroll
        for (int e = 0; e < 2; ++e) {
            const int col = 8 * t + tig * 2 + e;
            b1v[t][e] = __ldg(&b1[col]);
            w2v[t][e][0] = __ldg(&w2[col * H_DIM + 0]);
            w2v[t][e][1] = __ldg(&w2[col * H_DIM + 1]);
            w2v[t][e][2] = __ldg(&w2[col * H_DIM + 2]);
        }
    const float bb0 = __ldg(&b2[0]), bb1 = __ldg(&b2[1]), bb2 = __ldg(&b2[2]);

    float* swp = swbuf[wid];
    const float2* X2 = reinterpret_cast<const float2*>(X);

    const int warp0 = blockIdx.x * 4 + wid;
    const int nwarp = gridDim.x * 4;

    for (int seg = warp0; seg < G; seg += nwarp) {
        const int s0  = g_segstart[seg];
        const int s1  = g_segstart[seg + 1];
        const int cnt = s1 - s0;
        float* outg = out + (size_t)seg * (D_DIM * H_DIM);

        if (cnt <= 0) {
            float2 z = make_float2(0.f, 0.f);
            float2* o2 = reinterpret_cast<float2*>(outg);
#pragma unroll
            for (int q = 0; q < 3; ++q) o2[lane + 32 * q] = z;
            continue;
        }

        // =========== Phase A: scores (mma.sync) -> smem or gmem ===========
        const bool fast = (cnt <= SEG_CAP);
        const int ntile = (cnt + 15) >> 4;
        for (int ti = 0; ti < ntile; ++ti) {
            float acc[4][4];
#pragma unroll
            for (int t = 0; t < 4; ++t) {
                acc[t][0] = 0.f; acc[t][1] = 0.f; acc[t][2] = 0.f; acc[t][3] = 0.f;
            }
            const int r0 = s0 + ti * 16 + g;
            const int r1 = r0 + 8;
            const float* x0 = X + (size_t)(r0 < s1 ? r0 : s1 - 1) * D_DIM;
            const float* x1 = X + (size_t)(r1 < s1 ? r1 : s1 - 1) * D_DIM;

#pragma unroll
            for (int s = 0; s < 4; ++s) {
                const int ks = 16 * s + tig * 2;
                float2 v0 = *reinterpret_cast<const float2*>(x0 + ks);
                float2 v1 = *reinterpret_cast<const float2*>(x1 + ks);
                float2 v2 = *reinterpret_cast<const float2*>(x0 + ks + 8);
                float2 v3 = *reinterpret_cast<const float2*>(x1 + ks + 8);

                uint32_t ah0 = pk2bf(v0.x, v0.y);
                uint32_t ah1 = pk2bf(v1.x, v1.y);
                uint32_t ah2 = pk2bf(v2.x, v2.y);
                uint32_t ah3 = pk2bf(v3.x, v3.y);
                uint32_t al0 = pk2bf(v0.x - bfhi(v0.x), v0.y - bfhi(v0.y));
                uint32_t al1 = pk2bf(v1.x - bfhi(v1.x), v1.y - bfhi(v1.y));
                uint32_t al2 = pk2bf(v2.x - bfhi(v2.x), v2.y - bfhi(v2.y));
                uint32_t al3 = pk2bf(v3.x - bfhi(v3.x), v3.y - bfhi(v3.y));

#pragma unroll
                for (int t = 0; t < 4; ++t) {
                    mma16816(acc[t], ah0, ah1, ah2, ah3, bh[t][s][0], bh[t][s][1]);
                    mma16816(acc[t], ah0, ah1, ah2, ah3, bl[t][s][0], bl[t][s][1]);
                    mma16816(acc[t], al0, al1, al2, al3, bh[t][s][0], bh[t][s][1]);
                }
            }

#pragma unroll
            for (int row = 0; row < 2; ++row) {
                float q0 = 0.f, q1 = 0.f, q2 = 0.f;
#pragma unroll
                for (int t = 0; t < 4; ++t)
#pragma unroll
                    for (int e = 0; e < 2; ++e) {
                        float h = acc[t][row * 2 + e] + b1v[t][e];
                        float act = __fdividef(h, 1.0f + __expf(-h));
                        q0 = fmaf(act, w2v[t][e][0], q0);
                        q1 = fmaf(act, w2v[t][e][1], q1);
                        q2 = fmaf(act, w2v[t][e][2], q2);
                    }
                q0 += __shfl_xor_sync(0xffffffffu, q0, 1);
                q0 += __shfl_xor_sync(0xffffffffu, q0, 2);
                q1 += __shfl_xor_sync(0xffffffffu, q1, 1);
                q1 += __shfl_xor_sync(0xffffffffu, q1, 2);
                q2 += __shfl_xor_sync(0xffffffffu, q2, 1);
                q2 += __shfl_xor_sync(0xffffffffu, q2, 2);

                const int idx = ti * 16 + g + 8 * row;
                if (tig == 0 && idx < cnt) {
                    if (fast) {
                        swp[idx * 3 + 0] = q0 + bb0;
                        swp[idx * 3 + 1] = q1 + bb1;
                        swp[idx * 3 + 2] = q2 + bb2;
                    } else {
                        size_t o = (size_t)(s0 + idx) * H_DIM;
                        g_scores[o + 0] = q0 + bb0;
                        g_scores[o + 1] = q1 + bb1;
                        g_scores[o + 2] = q2 + bb2;
                    }
                }
            }
        }
        __syncwarp();

        float m0 = -3.4e38f, m1 = -3.4e38f, m2 = -3.4e38f;
        float r0v, r1v, r2v;
        ull acc0 = 0ull, acc1 = 0ull, acc2 = 0ull;

        if (fast) {
            // =========== Phase B: softmax over smem scores ===========
#pragma unroll
            for (int q = 0; q < 4; ++q) {
                int a = lane + 32 * q;
                if (a < cnt) {
                    m0 = fmaxf(m0, swp[a * 3 + 0]);
                    m1 = fmaxf(m1, swp[a * 3 + 1]);
                    m2 = fmaxf(m2, swp[a * 3 + 2]);
                }
            }
#pragma unroll
            for (int off = 16; off; off >>= 1) {
                m0 = fmaxf(m0, __shfl_xor_sync(0xffffffffu, m0, off));
                m1 = fmaxf(m1, __shfl_xor_sync(0xffffffffu, m1, off));
                m2 = fmaxf(m2, __shfl_xor_sync(0xffffffffu, m2, off));
            }
            float e0 = 0.f, e1 = 0.f, e2 = 0.f;
            float ex[4][3];
#pragma unroll
            for (int q = 0; q < 4; ++q) {
                int a = lane + 32 * q;
                if (a < cnt) {
                    ex[q][0] = __expf(swp[a * 3 + 0] - m0); e0 += ex[q][0];
                    ex[q][1] = __expf(swp[a * 3 + 1] - m1); e1 += ex[q][1];
                    ex[q][2] = __expf(swp[a * 3 + 2] - m2); e2 += ex[q][2];
                }
            }
#pragma unroll
            for (int off = 16; off; off >>= 1) {
                e0 += __shfl_xor_sync(0xffffffffu, e0, off);
                e1 += __shfl_xor_sync(0xffffffffu, e1, off);
                e2 += __shfl_xor_sync(0xffffffffu, e2, off);
            }
            r0v = 1.0f / e0; r1v = 1.0f / e1; r2v = 1.0f / e2;
            __syncwarp();
#pragma unroll
            for (int q = 0; q < 4; ++q) {
                int a = lane + 32 * q;
                if (a < cnt) {
                    swp[a * 3 + 0] = ex[q][0] * r0v;
                    swp[a * 3 + 1] = ex[q][1] * r1v;
                    swp[a * 3 + 2] = ex[q][2] * r2v;
                }
            }
            __syncwarp();

            // =========== Phase C: pooling (X rows are L1-hot) ===========
#pragma unroll 4
            for (int a = 0; a < cnt; ++a) {
                float2 xv = X2[(size_t)(s0 + a) * (D_DIM / 2) + lane];
                ull xx = *reinterpret_cast<ull*>(&xv);
                acc0 = fma2(xx, pack2(swp[a * 3 + 0]), acc0);
                acc1 = fma2(xx, pack2(swp[a * 3 + 1]), acc1);
                acc2 = fma2(xx, pack2(swp[a * 3 + 2]), acc2);
            }
        } else {
            // =========== rare big-segment path via g_scores ===========
            for (int n = s0 + lane; n < s1; n += 32) {
                size_t o = (size_t)n * H_DIM;
                m0 = fmaxf(m0, g_scores[o + 0]);
                m1 = fmaxf(m1, g_scores[o + 1]);
                m2 = fmaxf(m2, g_scores[o + 2]);
            }
#pragma unroll
            for (int off = 16; off; off >>= 1) {
                m0 = fmaxf(m0, __shfl_xor_sync(0xffffffffu, m0, off));
                m1 = fmaxf(m1, __shfl_xor_sync(0xffffffffu, m1, off));
                m2 = fmaxf(m2, __shfl_xor_sync(0xffffffffu, m2, off));
            }
            float e0 = 0.f, e1 = 0.f, e2 = 0.f;
            for (int n = s0 + lane; n < s1; n += 32) {
                size_t o = (size_t)n * H_DIM;
                e0 += __expf(g_scores[o + 0] - m0);
                e1 += __expf(g_scores[o + 1] - m1);
                e2 += __expf(g_scores[o + 2] - m2);
            }
#pragma unroll
            for (int off = 16; off; off >>= 1) {
                e0 += __shfl_xor_sync(0xffffffffu, e0, off);
                e1 += __shfl_xor_sync(0xffffffffu, e1, off);
                e2 += __shfl_xor_sync(0xffffffffu, e2, off);
            }
            r0v = 1.0f / e0; r1v = 1.0f / e1; r2v = 1.0f / e2;

            for (int base = 0; base < cnt; base += SEG_CAP) {
                int c = min(SEG_CAP, cnt - base);
#pragma unroll
                for (int q = 0; q < 4; ++q) {
                    int a = lane + 32 * q;
                    if (a < c) {
                        size_t o = (size_t)(s0 + base + a) * H_DIM;
                        swp[a * 3 + 0] = __expf(g_scores[o + 0] - m0) * r0v;
                        swp[a * 3 + 1] = __expf(g_scores[o + 1] - m1) * r1v;
                        swp[a * 3 + 2] = __expf(g_scores[o + 2] - m2) * r2v;
                    }
                }
                __syncwarp();
#pragma unroll 4
                for (int a = 0; a < c; ++a) {
                    float2 xv = X2[(size_t)(s0 + base + a) * (D_DIM / 2) + lane];
                    ull xx = *reinterpret_cast<ull*>(&xv);
                    acc0 = fma2(xx, pack2(swp[a * 3 + 0]), acc0);
                    acc1 = fma2(xx, pack2(swp[a * 3 + 1]), acc1);
                    acc2 = fma2(xx, pack2(swp[a * 3 + 2]), acc2);
                }
                __syncwarp();
            }
        }

        // ---- write out: lane owns d = 2*lane, 2*lane+1 ; layout [g][d][h] ----
        float v00, v01, v10, v11, v20, v21;
        unpack2(acc0, v00, v01);
        unpack2(acc1, v10, v11);
        unpack2(acc2, v20, v21);
        float* po = outg + lane * 6;
        po[0] = v00; po[1] = v10; po[2] = v20;
        po[3] = v01; po[4] = v11; po[5] = v21;
    }
}

// ---------------------------------------------------------------------------
extern "C" void kernel_launch(void* const* d_in, const int* in_sizes, int n_in,
                              void* d_out, int out_size)
{
    const float* X     = (const float*)d_in[0];
    const float* w1    = (const float*)d_in[1];
    const float* b1    = (const float*)d_in[2];
    const float* w2    = (const float*)d_in[3];
    const float* b2    = (const float*)d_in[4];
    const int*   owner = (const int*)  d_in[5];

    const int N = in_sizes[5];
    const int G = out_size / (D_DIM * H_DIM);

    k_bounds<<<(N + 255) / 256, 256>>>(owner, N, G);
    k_fused<<<444, 128>>>(X, w1, b1, w2, b2, (float*)d_out, N, G);
}

// round 7
// speedup vs baseline: 1.2605x; 1.2605x over previous
#include <cuda_runtime.h>
#include <cuda_bf16.h>
#include <cstdint>

// Problem shape (fixed by dataset): N=2,000,000 atoms, D=64, HID=32, H=3, G=50,000
#define D_DIM   64
#define HID_DIM 32
#define H_DIM   3

#define MAX_N 2000000
#define MAX_G 50000
#define SEG_CAP 128

typedef unsigned long long ull;

// Scratch (device globals: no allocation allowed in kernel_launch)
__device__ float g_scores[(size_t)MAX_N * H_DIM];   // 24 MB
__device__ int   g_segstart[MAX_G + 1];

// ---------------- packed fp32x2 helpers ----------------
__device__ __forceinline__ ull pack2(float v) {
    ull r; asm("mov.b64 %0, {%1, %1};" : "=l"(r) : "f"(v)); return r;
}
__device__ __forceinline__ ull fma2(ull a, ull b, ull c) {
    ull d; asm("fma.rn.f32x2 %0, %1, %2, %3;" : "=l"(d) : "l"(a), "l"(b), "l"(c)); return d;
}
__device__ __forceinline__ void unpack2(ull v, float& lo, float& hi) {
    asm("mov.b64 {%0, %1}, %2;" : "=f"(lo), "=f"(hi) : "l"(v));
}

// ---------------- bf16 helpers ----------------
__device__ __forceinline__ uint32_t pk2bf(float a, float b) {
    __nv_bfloat162 h = __floats2bfloat162_rn(a, b);
    return *reinterpret_cast<uint32_t*>(&h);
}
__device__ __forceinline__ float bfhi(float x) {
    return __bfloat162float(__float2bfloat16_rn(x));
}

// warp-level tensor-core MMA (sm_80+ feature set; compiles for plain sm_103)
__device__ __forceinline__ void mma16816(float c[4],
    uint32_t a0, uint32_t a1, uint32_t a2, uint32_t a3,
    uint32_t b0, uint32_t b1)
{
    asm volatile(
        "mma.sync.aligned.m16n8k16.row.col.f32.bf16.bf16.f32 "
        "{%0,%1,%2,%3}, {%4,%5,%6,%7}, {%8,%9}, {%0,%1,%2,%3};"
        : "+f"(c[0]), "+f"(c[1]), "+f"(c[2]), "+f"(c[3])
        : "r"(a0), "r"(a1), "r"(a2), "r"(a3), "r"(b0), "r"(b1));
}

// ---------------------------------------------------------------------------
// Kernel 1 (tensor-core, mma.sync): per-atom MLP scores.
// B fragments + epilogue constants live in SMEM (lane-indexed, warp-shared)
// -> low register count -> high occupancy -> X-stream bound.
// ---------------------------------------------------------------------------
__global__ __launch_bounds__(128) void k_scores_mma(
    const float* __restrict__ X,
    const float* __restrict__ w1, const float* __restrict__ b1,
    const float* __restrict__ w2, const float* __restrict__ b2,
    int N, int ntiles)
{
    // sB[t][s][lane] = {bh0, bh1, bl0, bl1}      (8 KB)
    // sE[t][e][lane] = {b1, w2_0, w2_1, w2_2}    (4 KB)
    __shared__ uint4 sB[4][4][32];
    __shared__ uint4 sE[4][2][32];

    const int lane = threadIdx.x & 31;
    const int wid  = threadIdx.x >> 5;
    const int g    = lane >> 2;   // row group 0..7
    const int tig  = lane & 3;    // thread-in-group

    if (wid == 0) {
#pragma unroll
        for (int t = 0; t < 4; ++t) {
            const int col = g + 8 * t;
#pragma unroll
            for (int s = 0; s < 4; ++s) {
                const int k0 = tig * 2 + 16 * s;
                float w00 = __ldg(&w1[(k0 + 0) * HID_DIM + col]);
                float w01 = __ldg(&w1[(k0 + 1) * HID_DIM + col]);
                float w08 = __ldg(&w1[(k0 + 8) * HID_DIM + col]);
                float w09 = __ldg(&w1[(k0 + 9) * HID_DIM + col]);
                uint4 v;
                v.x = pk2bf(w00, w01);
                v.y = pk2bf(w08, w09);
                v.z = pk2bf(w00 - bfhi(w00), w01 - bfhi(w01));
                v.w = pk2bf(w08 - bfhi(w08), w09 - bfhi(w09));
                sB[t][s][lane] = v;
            }
#pragma unroll
            for (int e = 0; e < 2; ++e) {
                const int col2 = 8 * t + tig * 2 + e;
                uint4 v;
                v.x = __float_as_uint(__ldg(&b1[col2]));
                v.y = __float_as_uint(__ldg(&w2[col2 * H_DIM + 0]));
                v.z = __float_as_uint(__ldg(&w2[col2 * H_DIM + 1]));
                v.w = __float_as_uint(__ldg(&w2[col2 * H_DIM + 2]));
                sE[t][e][lane] = v;
            }
        }
    }
    __syncthreads();

    const float bb0 = __ldg(&b2[0]), bb1 = __ldg(&b2[1]), bb2 = __ldg(&b2[2]);

    const int warp0 = blockIdx.x * 4 + wid;
    const int nwarp = gridDim.x * 4;

    for (int tile = warp0; tile < ntiles; tile += nwarp) {
        float acc[4][4];
#pragma unroll
        for (int t = 0; t < 4; ++t) {
            acc[t][0] = 0.f; acc[t][1] = 0.f; acc[t][2] = 0.f; acc[t][3] = 0.f;
        }

        const int r0 = tile * 16 + g;
        const int r1 = r0 + 8;
        const float* x0 = X + (size_t)(r0 < N ? r0 : N - 1) * D_DIM;
        const float* x1 = X + (size_t)(r1 < N ? r1 : N - 1) * D_DIM;

#pragma unroll
        for (int s = 0; s < 4; ++s) {
            const int ks = 16 * s + tig * 2;
            float2 v0 = *reinterpret_cast<const float2*>(x0 + ks);
            float2 v1 = *reinterpret_cast<const float2*>(x1 + ks);
            float2 v2 = *reinterpret_cast<const float2*>(x0 + ks + 8);
            float2 v3 = *reinterpret_cast<const float2*>(x1 + ks + 8);

            uint32_t ah0 = pk2bf(v0.x, v0.y);
            uint32_t ah1 = pk2bf(v1.x, v1.y);
            uint32_t ah2 = pk2bf(v2.x, v2.y);
            uint32_t ah3 = pk2bf(v3.x, v3.y);
            uint32_t al0 = pk2bf(v0.x - bfhi(v0.x), v0.y - bfhi(v0.y));
            uint32_t al1 = pk2bf(v1.x - bfhi(v1.x), v1.y - bfhi(v1.y));
            uint32_t al2 = pk2bf(v2.x - bfhi(v2.x), v2.y - bfhi(v2.y));
            uint32_t al3 = pk2bf(v3.x - bfhi(v3.x), v3.y - bfhi(v3.y));

#pragma unroll
            for (int t = 0; t < 4; ++t) {
                uint4 bf = sB[t][s][lane];
                mma16816(acc[t], ah0, ah1, ah2, ah3, bf.x, bf.y);   // xhi * whi
                mma16816(acc[t], ah0, ah1, ah2, ah3, bf.z, bf.w);   // xhi * wlo
                mma16816(acc[t], al0, al1, al2, al3, bf.x, bf.y);   // xlo * whi
            }
        }

        // ---- epilogue: +b1, SiLU, @w2, reduce over the 4-lane group ----
#pragma unroll
        for (int row = 0; row < 2; ++row) {
            float q0 = 0.f, q1 = 0.f, q2 = 0.f;
#pragma unroll
            for (int t = 0; t < 4; ++t) {
#pragma unroll
                for (int e = 0; e < 2; ++e) {
                    uint4 c = sE[t][e][lane];
                    float h = acc[t][row * 2 + e] + __uint_as_float(c.x);
                    float act = __fdividef(h, 1.0f + __expf(-h));
                    q0 = fmaf(act, __uint_as_float(c.y), q0);
                    q1 = fmaf(act, __uint_as_float(c.z), q1);
                    q2 = fmaf(act, __uint_as_float(c.w), q2);
                }
            }
            q0 += __shfl_xor_sync(0xffffffffu, q0, 1);
            q0 += __shfl_xor_sync(0xffffffffu, q0, 2);
            q1 += __shfl_xor_sync(0xffffffffu, q1, 1);
            q1 += __shfl_xor_sync(0xffffffffu, q1, 2);
            q2 += __shfl_xor_sync(0xffffffffu, q2, 1);
            q2 += __shfl_xor_sync(0xffffffffu, q2, 2);

            const int atom = tile * 16 + g + 8 * row;
            if (tig == 0 && atom < N) {
                size_t o = (size_t)atom * H_DIM;
                g_scores[o + 0] = q0 + bb0;
                g_scores[o + 1] = q1 + bb1;
                g_scores[o + 2] = q2 + bb2;
            }
        }
    }
}

// ---------------------------------------------------------------------------
// Kernel 2: segment boundaries from sorted owner array.
// ---------------------------------------------------------------------------
__global__ void k_bounds(const int* __restrict__ owner, int N, int G)
{
    int i = blockIdx.x * blockDim.x + threadIdx.x;
    if (i >= N) return;
    int o = owner[i];
    if (i == 0) {
        for (int g = 0; g <= o; ++g) g_segstart[g] = 0;
    } else {
        int po = owner[i - 1];
        for (int g = po + 1; g <= o; ++g) g_segstart[g] = i;
    }
    if (i == N - 1) {
        for (int g = o + 1; g <= G; ++g) g_segstart[g] = N;
    }
}

// ---------------------------------------------------------------------------
// Kernel 3: one WARP per segment (R5 version — performs at prediction).
// ---------------------------------------------------------------------------
__global__ __launch_bounds__(128) void k_pool(
    const float* __restrict__ X, float* __restrict__ out, int G)
{
    __shared__ float sw[4][SEG_CAP * H_DIM];

    const int warp = threadIdx.x >> 5;
    const int lane = threadIdx.x & 31;
    const int g    = blockIdx.x * 4 + warp;
    if (g >= G) return;

    const int s0  = g_segstart[g];
    const int s1  = g_segstart[g + 1];
    const int cnt = s1 - s0;

    float* outg = out + (size_t)g * (D_DIM * H_DIM);
    if (cnt <= 0) {
        for (int i = lane; i < D_DIM * H_DIM; i += 32) outg[i] = 0.f;
        return;
    }

    float* swp = sw[warp];
    const float2* X2 = reinterpret_cast<const float2*>(X);

    float m0 = -3.4e38f, m1 = -3.4e38f, m2 = -3.4e38f;
    float r0, r1, r2;
    ull acc0 = 0ull, acc1 = 0ull, acc2 = 0ull;

    if (cnt <= SEG_CAP) {
        float sc[4][3];
#pragma unroll
        for (int q = 0; q < 4; ++q) {
            int a = lane + 32 * q;
            if (a < cnt) {
                size_t o = (size_t)(s0 + a) * H_DIM;
                sc[q][0] = g_scores[o + 0];
                sc[q][1] = g_scores[o + 1];
                sc[q][2] = g_scores[o + 2];
                m0 = fmaxf(m0, sc[q][0]);
                m1 = fmaxf(m1, sc[q][1]);
                m2 = fmaxf(m2, sc[q][2]);
            }
        }
#pragma unroll
        for (int off = 16; off; off >>= 1) {
            m0 = fmaxf(m0, __shfl_xor_sync(0xffffffffu, m0, off));
            m1 = fmaxf(m1, __shfl_xor_sync(0xffffffffu, m1, off));
            m2 = fmaxf(m2, __shfl_xor_sync(0xffffffffu, m2, off));
        }
        float e0 = 0.f, e1 = 0.f, e2 = 0.f;
#pragma unroll
        for (int q = 0; q < 4; ++q) {
            int a = lane + 32 * q;
            if (a < cnt) {
                sc[q][0] = __expf(sc[q][0] - m0); e0 += sc[q][0];
                sc[q][1] = __expf(sc[q][1] - m1); e1 += sc[q][1];
                sc[q][2] = __expf(sc[q][2] - m2); e2 += sc[q][2];
            }
        }
#pragma unroll
        for (int off = 16; off; off >>= 1) {
            e0 += __shfl_xor_sync(0xffffffffu, e0, off);
            e1 += __shfl_xor_sync(0xffffffffu, e1, off);
            e2 += __shfl_xor_sync(0xffffffffu, e2, off);
        }
        r0 = 1.0f / e0; r1 = 1.0f / e1; r2 = 1.0f / e2;
#pragma unroll
        for (int q = 0; q < 4; ++q) {
            int a = lane + 32 * q;
            if (a < cnt) {
                swp[a * 3 + 0] = sc[q][0] * r0;
                swp[a * 3 + 1] = sc[q][1] * r1;
                swp[a * 3 + 2] = sc[q][2] * r2;
            }
        }
        __syncwarp();

#pragma unroll 4
        for (int a = 0; a < cnt; ++a) {
            float2 xv = X2[(size_t)(s0 + a) * (D_DIM / 2) + lane];
            ull xx = *reinterpret_cast<ull*>(&xv);
            acc0 = fma2(xx, pack2(swp[a * 3 + 0]), acc0);
            acc1 = fma2(xx, pack2(swp[a * 3 + 1]), acc1);
            acc2 = fma2(xx, pack2(swp[a * 3 + 2]), acc2);
        }
    } else {
        for (int n = s0 + lane; n < s1; n += 32) {
            size_t o = (size_t)n * H_DIM;
            m0 = fmaxf(m0, g_scores[o + 0]);
            m1 = fmaxf(m1, g_scores[o + 1]);
            m2 = fmaxf(m2, g_scores[o + 2]);
        }
#pragma unroll
        for (int off = 16; off; off >>= 1) {
            m0 = fmaxf(m0, __shfl_xor_sync(0xffffffffu, m0, off));
            m1 = fmaxf(m1, __shfl_xor_sync(0xffffffffu, m1, off));
            m2 = fmaxf(m2, __shfl_xor_sync(0xffffffffu, m2, off));
        }
        float e0 = 0.f, e1 = 0.f, e2 = 0.f;
        for (int n = s0 + lane; n < s1; n += 32) {
            size_t o = (size_t)n * H_DIM;
            e0 += __expf(g_scores[o + 0] - m0);
            e1 += __expf(g_scores[o + 1] - m1);
            e2 += __expf(g_scores[o + 2] - m2);
        }
#pragma unroll
        for (int off = 16; off; off >>= 1) {
            e0 += __shfl_xor_sync(0xffffffffu, e0, off);
            e1 += __shfl_xor_sync(0xffffffffu, e1, off);
            e2 += __shfl_xor_sync(0xffffffffu, e2, off);
        }
        r0 = 1.0f / e0; r1 = 1.0f / e1; r2 = 1.0f / e2;

        for (int base = 0; base < cnt; base += SEG_CAP) {
            int c = min(SEG_CAP, cnt - base);
#pragma unroll
            for (int q = 0; q < 4; ++q) {
                int a = lane + 32 * q;
                if (a < c) {
                    size_t o = (size_t)(s0 + base + a) * H_DIM;
                    swp[a * 3 + 0] = __expf(g_scores[o + 0] - m0) * r0;
                    swp[a * 3 + 1] = __expf(g_scores[o + 1] - m1) * r1;
                    swp[a * 3 + 2] = __expf(g_scores[o + 2] - m2) * r2;
                }
            }
            __syncwarp();
#pragma unroll 4
            for (int a = 0; a < c; ++a) {
                float2 xv = X2[(size_t)(s0 + base + a) * (D_DIM / 2) + lane];
                ull xx = *reinterpret_cast<ull*>(&xv);
                acc0 = fma2(xx, pack2(swp[a * 3 + 0]), acc0);
                acc1 = fma2(xx, pack2(swp[a * 3 + 1]), acc1);
                acc2 = fma2(xx, pack2(swp[a * 3 + 2]), acc2);
            }
            __syncwarp();
        }
    }

    float v00, v01, v10, v11, v20, v21;
    unpack2(acc0, v00, v01);
    unpack2(acc1, v10, v11);
    unpack2(acc2, v20, v21);
    float* po = outg + lane * 6;
    po[0] = v00; po[1] = v10; po[2] = v20;
    po[3] = v01; po[4] = v11; po[5] = v21;
}

// ---------------------------------------------------------------------------
extern "C" void kernel_launch(void* const* d_in, const int* in_sizes, int n_in,
                              void* d_out, int out_size)
{
    const float* X     = (const float*)d_in[0];
    const float* w1    = (const float*)d_in[1];
    const float* b1    = (const float*)d_in[2];
    const float* w2    = (const float*)d_in[3];
    const float* b2    = (const float*)d_in[4];
    const int*   owner = (const int*)  d_in[5];

    const int N = in_sizes[5];
    const int G = out_size / (D_DIM * H_DIM);
    const int ntiles = (N + 15) / 16;

    k_scores_mma<<<1184, 128>>>(X, w1, b1, w2, b2, N, ntiles);
    k_bounds<<<(N + 255) / 256, 256>>>(owner, N, G);
    k_pool<<<(G + 3) / 4, 128>>>(X, (float*)d_out, G);
}

// round 8
// speedup vs baseline: 1.2816x; 1.0167x over previous
#include <cuda_runtime.h>
#include <cuda_bf16.h>
#include <cstdint>

// Problem shape (fixed by dataset): N=2,000,000 atoms, D=64, HID=32, H=3, G=50,000
#define D_DIM   64
#define HID_DIM 32
#define H_DIM   3

#define MAX_N 2000000
#define MAX_G 50000
#define SEG_CAP 128

typedef unsigned long long ull;

// Scratch (device globals)
__device__ float g_scores[(size_t)MAX_N * H_DIM];   // big-segment fallback only
__device__ int   g_segstart[MAX_G + 1];

// ---------------- packed fp32x2 helpers ----------------
__device__ __forceinline__ ull pack2(float v) {
    ull r; asm("mov.b64 %0, {%1, %1};" : "=l"(r) : "f"(v)); return r;
}
__device__ __forceinline__ ull fma2(ull a, ull b, ull c) {
    ull d; asm("fma.rn.f32x2 %0, %1, %2, %3;" : "=l"(d) : "l"(a), "l"(b), "l"(c)); return d;
}
__device__ __forceinline__ void unpack2(ull v, float& lo, float& hi) {
    asm("mov.b64 {%0, %1}, %2;" : "=f"(lo), "=f"(hi) : "l"(v));
}

// ---------------- bf16 helpers ----------------
__device__ __forceinline__ uint32_t pk2bf(float a, float b) {
    __nv_bfloat162 h = __floats2bfloat162_rn(a, b);
    return *reinterpret_cast<uint32_t*>(&h);
}
__device__ __forceinline__ float bfhi(float x) {
    return __bfloat162float(__float2bfloat16_rn(x));
}

// warp-level tensor-core MMA (sm_80+ feature set; compiles for plain sm_103)
__device__ __forceinline__ void mma16816(float c[4],
    uint32_t a0, uint32_t a1, uint32_t a2, uint32_t a3,
    uint32_t b0, uint32_t b1)
{
    asm volatile(
        "mma.sync.aligned.m16n8k16.row.col.f32.bf16.bf16.f32 "
        "{%0,%1,%2,%3}, {%4,%5,%6,%7}, {%8,%9}, {%0,%1,%2,%3};"
        : "+f"(c[0]), "+f"(c[1]), "+f"(c[2]), "+f"(c[3])
        : "r"(a0), "r"(a1), "r"(a2), "r"(a3), "r"(b0), "r"(b1));
}

// ---------------------------------------------------------------------------
// Kernel 1: segment boundaries from sorted owner array.
// ---------------------------------------------------------------------------
__global__ void k_bounds(const int* __restrict__ owner, int N, int G)
{
    int i = blockIdx.x * blockDim.x + threadIdx.x;
    if (i >= N) return;
    int o = owner[i];
    if (i == 0) {
        for (int g = 0; g <= o; ++g) g_segstart[g] = 0;
    } else {
        int po = owner[i - 1];
        for (int g = po + 1; g <= o; ++g) g_segstart[g] = i;
    }
    if (i == N - 1) {
        for (int g = o + 1; g <= G; ++g) g_segstart[g] = N;
    }
}

// ---------------------------------------------------------------------------
// Kernel 2 (FUSED, low-reg): one persistent warp per segment.
//   B fragments + epilogue constants in SMEM (warp-shared, lane-indexed)
//   Phase A: scores via 3-term double-bf16 mma.sync -> per-warp smem
//   Phase B: warp-shuffle softmax
//   Phase C: weighted pooling (X rows L2-hot)
// ---------------------------------------------------------------------------
__global__ __launch_bounds__(128) void k_fused(
    const float* __restrict__ X,
    const float* __restrict__ w1, const float* __restrict__ b1,
    const float* __restrict__ w2, const float* __restrict__ b2,
    float* __restrict__ out, int N, int G)
{
    __shared__ uint4 sB[4][4][32];              // 8 KB  {bh0,bh1,bl0,bl1}
    __shared__ uint4 sE[4][2][32];              // 4 KB  {b1, w2_0, w2_1, w2_2}
    __shared__ float swbuf[4][SEG_CAP * H_DIM]; // 6 KB

    const int lane = threadIdx.x & 31;
    const int wid  = threadIdx.x >> 5;
    const int g    = lane >> 2;   // row group 0..7
    const int tig  = lane & 3;    // thread-in-group

    if (wid == 0) {
#pragma unroll
        for (int t = 0; t < 4; ++t) {
            const int col = g + 8 * t;
#pragma unroll
            for (int s = 0; s < 4; ++s) {
                const int k0 = tig * 2 + 16 * s;
                float w00 = __ldg(&w1[(k0 + 0) * HID_DIM + col]);
                float w01 = __ldg(&w1[(k0 + 1) * HID_DIM + col]);
                float w08 = __ldg(&w1[(k0 + 8) * HID_DIM + col]);
                float w09 = __ldg(&w1[(k0 + 9) * HID_DIM + col]);
                uint4 v;
                v.x = pk2bf(w00, w01);
                v.y = pk2bf(w08, w09);
                v.z = pk2bf(w00 - bfhi(w00), w01 - bfhi(w01));
                v.w = pk2bf(w08 - bfhi(w08), w09 - bfhi(w09));
                sB[t][s][lane] = v;
            }
#pragma unroll
            for (int e = 0; e < 2; ++e) {
                const int col2 = 8 * t + tig * 2 + e;
                uint4 v;
                v.x = __float_as_uint(__ldg(&b1[col2]));
                v.y = __float_as_uint(__ldg(&w2[col2 * H_DIM + 0]));
                v.z = __float_as_uint(__ldg(&w2[col2 * H_DIM + 1]));
                v.w = __float_as_uint(__ldg(&w2[col2 * H_DIM + 2]));
                sE[t][e][lane] = v;
            }
        }
    }
    __syncthreads();

    const float bb0 = __ldg(&b2[0]), bb1 = __ldg(&b2[1]), bb2 = __ldg(&b2[2]);

    float* swp = swbuf[wid];
    const float2* X2 = reinterpret_cast<const float2*>(X);

    const int warp0 = blockIdx.x * 4 + wid;
    const int nwarp = gridDim.x * 4;

    for (int seg = warp0; seg < G; seg += nwarp) {
        const int s0  = g_segstart[seg];
        const int s1  = g_segstart[seg + 1];
        const int cnt = s1 - s0;
        float* outg = out + (size_t)seg * (D_DIM * H_DIM);

        if (cnt <= 0) {
            float2 z = make_float2(0.f, 0.f);
            float2* o2 = reinterpret_cast<float2*>(outg);
#pragma unroll
            for (int q = 0; q < 3; ++q) o2[lane + 32 * q] = z;
            continue;
        }

        // =========== Phase A: scores (mma.sync) -> smem or gmem ===========
        const bool fast = (cnt <= SEG_CAP);
        const int ntile = (cnt + 15) >> 4;
        for (int ti = 0; ti < ntile; ++ti) {
            float acc[4][4];
#pragma unroll
            for (int t = 0; t < 4; ++t) {
                acc[t][0] = 0.f; acc[t][1] = 0.f; acc[t][2] = 0.f; acc[t][3] = 0.f;
            }
            const int r0 = s0 + ti * 16 + g;
            const int r1 = r0 + 8;
            const float* x0 = X + (size_t)(r0 < s1 ? r0 : s1 - 1) * D_DIM;
            const float* x1 = X + (size_t)(r1 < s1 ? r1 : s1 - 1) * D_DIM;

#pragma unroll
            for (int s = 0; s < 4; ++s) {
                const int ks = 16 * s + tig * 2;
                float2 v0 = *reinterpret_cast<const float2*>(x0 + ks);
                float2 v1 = *reinterpret_cast<const float2*>(x1 + ks);
                float2 v2 = *reinterpret_cast<const float2*>(x0 + ks + 8);
                float2 v3 = *reinterpret_cast<const float2*>(x1 + ks + 8);

                uint32_t ah0 = pk2bf(v0.x, v0.y);
                uint32_t ah1 = pk2bf(v1.x, v1.y);
                uint32_t ah2 = pk2bf(v2.x, v2.y);
                uint32_t ah3 = pk2bf(v3.x, v3.y);
                uint32_t al0 = pk2bf(v0.x - bfhi(v0.x), v0.y - bfhi(v0.y));
                uint32_t al1 = pk2bf(v1.x - bfhi(v1.x), v1.y - bfhi(v1.y));
                uint32_t al2 = pk2bf(v2.x - bfhi(v2.x), v2.y - bfhi(v2.y));
                uint32_t al3 = pk2bf(v3.x - bfhi(v3.x), v3.y - bfhi(v3.y));

#pragma unroll
                for (int t = 0; t < 4; ++t) {
                    uint4 bf = sB[t][s][lane];
                    mma16816(acc[t], ah0, ah1, ah2, ah3, bf.x, bf.y);
                    mma16816(acc[t], ah0, ah1, ah2, ah3, bf.z, bf.w);
                    mma16816(acc[t], al0, al1, al2, al3, bf.x, bf.y);
                }
            }

#pragma unroll
            for (int row = 0; row < 2; ++row) {
                float q0 = 0.f, q1 = 0.f, q2 = 0.f;
#pragma unroll
                for (int t = 0; t < 4; ++t) {
#pragma unroll
                    for (int e = 0; e < 2; ++e) {
                        uint4 c = sE[t][e][lane];
                        float h = acc[t][row * 2 + e] + __uint_as_float(c.x);
                        float act = __fdividef(h, 1.0f + __expf(-h));
                        q0 = fmaf(act, __uint_as_float(c.y), q0);
                        q1 = fmaf(act, __uint_as_float(c.z), q1);
                        q2 = fmaf(act, __uint_as_float(c.w), q2);
                    }
                }
                q0 += __shfl_xor_sync(0xffffffffu, q0, 1);
                q0 += __shfl_xor_sync(0xffffffffu, q0, 2);
                q1 += __shfl_xor_sync(0xffffffffu, q1, 1);
                q1 += __shfl_xor_sync(0xffffffffu, q1, 2);
                q2 += __shfl_xor_sync(0xffffffffu, q2, 1);
                q2 += __shfl_xor_sync(0xffffffffu, q2, 2);

                const int idx = ti * 16 + g + 8 * row;
                if (tig == 0 && idx < cnt) {
                    if (fast) {
                        swp[idx * 3 + 0] = q0 + bb0;
                        swp[idx * 3 + 1] = q1 + bb1;
                        swp[idx * 3 + 2] = q2 + bb2;
                    } else {
                        size_t o = (size_t)(s0 + idx) * H_DIM;
                        g_scores[o + 0] = q0 + bb0;
                        g_scores[o + 1] = q1 + bb1;
                        g_scores[o + 2] = q2 + bb2;
                    }
                }
            }
        }
        __syncwarp();

        float m0 = -3.4e38f, m1 = -3.4e38f, m2 = -3.4e38f;
        float r0v, r1v, r2v;
        ull acc0 = 0ull, acc1 = 0ull, acc2 = 0ull;

        if (fast) {
            // =========== Phase B: softmax over smem scores ===========
#pragma unroll
            for (int q = 0; q < 4; ++q) {
                int a = lane + 32 * q;
                if (a < cnt) {
                    m0 = fmaxf(m0, swp[a * 3 + 0]);
                    m1 = fmaxf(m1, swp[a * 3 + 1]);
                    m2 = fmaxf(m2, swp[a * 3 + 2]);
                }
            }
#pragma unroll
            for (int off = 16; off; off >>= 1) {
                m0 = fmaxf(m0, __shfl_xor_sync(0xffffffffu, m0, off));
                m1 = fmaxf(m1, __shfl_xor_sync(0xffffffffu, m1, off));
                m2 = fmaxf(m2, __shfl_xor_sync(0xffffffffu, m2, off));
            }
            float e0 = 0.f, e1 = 0.f, e2 = 0.f;
            float ex[4][3];
#pragma unroll
            for (int q = 0; q < 4; ++q) {
                int a = lane + 32 * q;
                if (a < cnt) {
                    ex[q][0] = __expf(swp[a * 3 + 0] - m0); e0 += ex[q][0];
                    ex[q][1] = __expf(swp[a * 3 + 1] - m1); e1 += ex[q][1];
                    ex[q][2] = __expf(swp[a * 3 + 2] - m2); e2 += ex[q][2];
                }
            }
#pragma unroll
            for (int off = 16; off; off >>= 1) {
                e0 += __shfl_xor_sync(0xffffffffu, e0, off);
                e1 += __shfl_xor_sync(0xffffffffu, e1, off);
                e2 += __shfl_xor_sync(0xffffffffu, e2, off);
            }
            r0v = 1.0f / e0; r1v = 1.0f / e1; r2v = 1.0f / e2;
            __syncwarp();
#pragma unroll
            for (int q = 0; q < 4; ++q) {
                int a = lane + 32 * q;
                if (a < cnt) {
                    swp[a * 3 + 0] = ex[q][0] * r0v;
                    swp[a * 3 + 1] = ex[q][1] * r1v;
                    swp[a * 3 + 2] = ex[q][2] * r2v;
                }
            }
            __syncwarp();

            // =========== Phase C: pooling (X rows L2-hot) ===========
#pragma unroll 4
            for (int a = 0; a < cnt; ++a) {
                float2 xv = X2[(size_t)(s0 + a) * (D_DIM / 2) + lane];
                ull xx = *reinterpret_cast<ull*>(&xv);
                acc0 = fma2(xx, pack2(swp[a * 3 + 0]), acc0);
                acc1 = fma2(xx, pack2(swp[a * 3 + 1]), acc1);
                acc2 = fma2(xx, pack2(swp[a * 3 + 2]), acc2);
            }
        } else {
            // =========== rare big-segment path via g_scores ===========
            for (int n = s0 + lane; n < s1; n += 32) {
                size_t o = (size_t)n * H_DIM;
                m0 = fmaxf(m0, g_scores[o + 0]);
                m1 = fmaxf(m1, g_scores[o + 1]);
                m2 = fmaxf(m2, g_scores[o + 2]);
            }
#pragma unroll
            for (int off = 16; off; off >>= 1) {
                m0 = fmaxf(m0, __shfl_xor_sync(0xffffffffu, m0, off));
                m1 = fmaxf(m1, __shfl_xor_sync(0xffffffffu, m1, off));
                m2 = fmaxf(m2, __shfl_xor_sync(0xffffffffu, m2, off));
            }
            float e0 = 0.f, e1 = 0.f, e2 = 0.f;
            for (int n = s0 + lane; n < s1; n += 32) {
                size_t o = (size_t)n * H_DIM;
                e0 += __expf(g_scores[o + 0] - m0);
                e1 += __expf(g_scores[o + 1] - m1);
                e2 += __expf(g_scores[o + 2] - m2);
            }
#pragma unroll
            for (int off = 16; off; off >>= 1) {
                e0 += __shfl_xor_sync(0xffffffffu, e0, off);
                e1 += __shfl_xor_sync(0xffffffffu, e1, off);
                e2 += __shfl_xor_sync(0xffffffffu, e2, off);
            }
            r0v = 1.0f / e0; r1v = 1.0f / e1; r2v = 1.0f / e2;

            for (int base = 0; base < cnt; base += SEG_CAP) {
                int c = min(SEG_CAP, cnt - base);
#pragma unroll
                for (int q = 0; q < 4; ++q) {
                    int a = lane + 32 * q;
                    if (a < c) {
                        size_t o = (size_t)(s0 + base + a) * H_DIM;
                        swp[a * 3 + 0] = __expf(g_scores[o + 0] - m0) * r0v;
                        swp[a * 3 + 1] = __expf(g_scores[o + 1] - m1) * r1v;
                        swp[a * 3 + 2] = __expf(g_scores[o + 2] - m2) * r2v;
                    }
                }
                __syncwarp();
#pragma unroll 4
                for (int a = 0; a < c; ++a) {
                    float2 xv = X2[(size_t)(s0 + base + a) * (D_DIM / 2) + lane];
                    ull xx = *reinterpret_cast<ull*>(&xv);
                    acc0 = fma2(xx, pack2(swp[a * 3 + 0]), acc0);
                    acc1 = fma2(xx, pack2(swp[a * 3 + 1]), acc1);
                    acc2 = fma2(xx, pack2(swp[a * 3 + 2]), acc2);
                }
                __syncwarp();
            }
        }

        // ---- write out: lane owns d = 2*lane, 2*lane+1 ; layout [g][d][h] ----
        float v00, v01, v10, v11, v20, v21;
        unpack2(acc0, v00, v01);
        unpack2(acc1, v10, v11);
        unpack2(acc2, v20, v21);
        float* po = outg + lane * 6;
        po[0] = v00; po[1] = v10; po[2] = v20;
        po[3] = v01; po[4] = v11; po[5] = v21;
    }
}

// ---------------------------------------------------------------------------
extern "C" void kernel_launch(void* const* d_in, const int* in_sizes, int n_in,
                              void* d_out, int out_size)
{
    const float* X     = (const float*)d_in[0];
    const float* w1    = (const float*)d_in[1];
    const float* b1    = (const float*)d_in[2];
    const float* w2    = (const float*)d_in[3];
    const float* b2    = (const float*)d_in[4];
    const int*   owner = (const int*)  d_in[5];

    const int N = in_sizes[5];
    const int G = out_size / (D_DIM * H_DIM);

    k_bounds<<<(N + 255) / 256, 256>>>(owner, N, G);
    k_fused<<<888, 128>>>(X, w1, b1, w2, b2, (float*)d_out, N, G);
}

// round 9
// speedup vs baseline: 1.2922x; 1.0083x over previous
#include <cuda_runtime.h>
#include <cuda_bf16.h>
#include <cstdint>

// Problem shape (fixed by dataset): N=2,000,000 atoms, D=64, HID=32, H=3, G=50,000
#define D_DIM   64
#define HID_DIM 32
#define H_DIM   3

#define MAX_N 2000000
#define MAX_G 50000
#define SEG_CAP 128

typedef unsigned long long ull;

// Scratch (device globals)
__device__ float g_scores[(size_t)MAX_N * H_DIM];   // big-segment fallback only
__device__ int   g_segstart[MAX_G + 1];

// ---------------- packed fp32x2 helpers ----------------
__device__ __forceinline__ ull pack2(float v) {
    ull r; asm("mov.b64 %0, {%1, %1};" : "=l"(r) : "f"(v)); return r;
}
__device__ __forceinline__ ull fma2(ull a, ull b, ull c) {
    ull d; asm("fma.rn.f32x2 %0, %1, %2, %3;" : "=l"(d) : "l"(a), "l"(b), "l"(c)); return d;
}
__device__ __forceinline__ void unpack2(ull v, float& lo, float& hi) {
    asm("mov.b64 {%0, %1}, %2;" : "=f"(lo), "=f"(hi) : "l"(v));
}

// ---------------- bf16 helpers ----------------
__device__ __forceinline__ uint32_t pk2bf(float a, float b) {
    __nv_bfloat162 h = __floats2bfloat162_rn(a, b);
    return *reinterpret_cast<uint32_t*>(&h);
}
__device__ __forceinline__ float bfhi(float x) {
    return __bfloat162float(__float2bfloat16_rn(x));
}

// warp-level tensor-core MMA (sm_80+ feature set; compiles for plain sm_103)
__device__ __forceinline__ void mma16816(float c[4],
    uint32_t a0, uint32_t a1, uint32_t a2, uint32_t a3,
    uint32_t b0, uint32_t b1)
{
    asm volatile(
        "mma.sync.aligned.m16n8k16.row.col.f32.bf16.bf16.f32 "
        "{%0,%1,%2,%3}, {%4,%5,%6,%7}, {%8,%9}, {%0,%1,%2,%3};"
        : "+f"(c[0]), "+f"(c[1]), "+f"(c[2]), "+f"(c[3])
        : "r"(a0), "r"(a1), "r"(a2), "r"(a3), "r"(b0), "r"(b1));
}

// ---------------------------------------------------------------------------
// Kernel 1: segment boundaries from sorted owner array.
// ---------------------------------------------------------------------------
__global__ void k_bounds(const int* __restrict__ owner, int N, int G)
{
    int i = blockIdx.x * blockDim.x + threadIdx.x;
    if (i >= N) return;
    int o = owner[i];
    if (i == 0) {
        for (int g = 0; g <= o; ++g) g_segstart[g] = 0;
    } else {
        int po = owner[i - 1];
        for (int g = po + 1; g <= o; ++g) g_segstart[g] = i;
    }
    if (i == N - 1) {
        for (int g = o + 1; g <= G; ++g) g_segstart[g] = N;
    }
}

// ---------------------------------------------------------------------------
// Kernel 2 (FUSED, low-reg, k-permuted): one persistent warp per segment.
//   k-axis permutation sigma(16s+2tig+8h+b) = 16s+4tig+2h+b applied to BOTH
//   X columns and w1 rows -> each lane's A-fragment per k-step is ONE float4
//   per row (LDG.128), halving L1 wavefronts of the score GEMM.
// ---------------------------------------------------------------------------
__global__ __launch_bounds__(128) void k_fused(
    const float* __restrict__ X,
    const float* __restrict__ w1, const float* __restrict__ b1,
    const float* __restrict__ w2, const float* __restrict__ b2,
    float* __restrict__ out, int N, int G)
{
    __shared__ uint4 sB[4][4][32];              // 8 KB  {bh0,bh1,bl0,bl1}
    __shared__ uint4 sE[4][2][32];              // 4 KB  {b1, w2_0, w2_1, w2_2}
    __shared__ float swbuf[4][SEG_CAP * H_DIM]; // 6 KB

    const int lane = threadIdx.x & 31;
    const int wid  = threadIdx.x >> 5;
    const int g    = lane >> 2;   // row group 0..7
    const int tig  = lane & 3;    // thread-in-group

    if (wid == 0) {
#pragma unroll
        for (int t = 0; t < 4; ++t) {
            const int col = g + 8 * t;
#pragma unroll
            for (int s = 0; s < 4; ++s) {
                // physical w1 rows under sigma: b0 <- {p0, p0+1}, b1 <- {p0+2, p0+3}
                const int p0 = 16 * s + 4 * tig;
                float w00 = __ldg(&w1[(p0 + 0) * HID_DIM + col]);
                float w01 = __ldg(&w1[(p0 + 1) * HID_DIM + col]);
                float w08 = __ldg(&w1[(p0 + 2) * HID_DIM + col]);
                float w09 = __ldg(&w1[(p0 + 3) * HID_DIM + col]);
                uint4 v;
                v.x = pk2bf(w00, w01);
                v.y = pk2bf(w08, w09);
                v.z = pk2bf(w00 - bfhi(w00), w01 - bfhi(w01));
                v.w = pk2bf(w08 - bfhi(w08), w09 - bfhi(w09));
                sB[t][s][lane] = v;
            }
#pragma unroll
            for (int e = 0; e < 2; ++e) {
                const int col2 = 8 * t + tig * 2 + e;
                uint4 v;
                v.x = __float_as_uint(__ldg(&b1[col2]));
                v.y = __float_as_uint(__ldg(&w2[col2 * H_DIM + 0]));
                v.z = __float_as_uint(__ldg(&w2[col2 * H_DIM + 1]));
                v.w = __float_as_uint(__ldg(&w2[col2 * H_DIM + 2]));
                sE[t][e][lane] = v;
            }
        }
    }
    __syncthreads();

    const float bb0 = __ldg(&b2[0]), bb1 = __ldg(&b2[1]), bb2 = __ldg(&b2[2]);

    float* swp = swbuf[wid];
    const float2* X2 = reinterpret_cast<const float2*>(X);

    const int warp0 = blockIdx.x * 4 + wid;
    const int nwarp = gridDim.x * 4;

    for (int seg = warp0; seg < G; seg += nwarp) {
        const int s0  = g_segstart[seg];
        const int s1  = g_segstart[seg + 1];
        const int cnt = s1 - s0;
        float* outg = out + (size_t)seg * (D_DIM * H_DIM);

        if (cnt <= 0) {
            float2 z = make_float2(0.f, 0.f);
            float2* o2 = reinterpret_cast<float2*>(outg);
#pragma unroll
            for (int q = 0; q < 3; ++q) o2[lane + 32 * q] = z;
            continue;
        }

        // =========== Phase A: scores (mma.sync, k-permuted loads) ===========
        const bool fast = (cnt <= SEG_CAP);
        const int ntile = (cnt + 15) >> 4;
        for (int ti = 0; ti < ntile; ++ti) {
            float acc[4][4];
#pragma unroll
            for (int t = 0; t < 4; ++t) {
                acc[t][0] = 0.f; acc[t][1] = 0.f; acc[t][2] = 0.f; acc[t][3] = 0.f;
            }
            const int r0 = s0 + ti * 16 + g;
            const int r1 = r0 + 8;
            const float* x0 = X + (size_t)(r0 < s1 ? r0 : s1 - 1) * D_DIM;
            const float* x1 = X + (size_t)(r1 < s1 ? r1 : s1 - 1) * D_DIM;

#pragma unroll
            for (int s = 0; s < 4; ++s) {
                const int ks = 16 * s + 4 * tig;   // physical col base (sigma)
                float4 u0 = *reinterpret_cast<const float4*>(x0 + ks);
                float4 u1 = *reinterpret_cast<const float4*>(x1 + ks);

                // slots: a0=(u0.x,u0.y) a1=(u1.x,u1.y) a2=(u0.z,u0.w) a3=(u1.z,u1.w)
                uint32_t ah0 = pk2bf(u0.x, u0.y);
                uint32_t ah1 = pk2bf(u1.x, u1.y);
                uint32_t ah2 = pk2bf(u0.z, u0.w);
                uint32_t ah3 = pk2bf(u1.z, u1.w);
                uint32_t al0 = pk2bf(u0.x - bfhi(u0.x), u0.y - bfhi(u0.y));
                uint32_t al1 = pk2bf(u1.x - bfhi(u1.x), u1.y - bfhi(u1.y));
                uint32_t al2 = pk2bf(u0.z - bfhi(u0.z), u0.w - bfhi(u0.w));
                uint32_t al3 = pk2bf(u1.z - bfhi(u1.z), u1.w - bfhi(u1.w));

#pragma unroll
                for (int t = 0; t < 4; ++t) {
                    uint4 bf = sB[t][s][lane];
                    mma16816(acc[t], ah0, ah1, ah2, ah3, bf.x, bf.y);
                    mma16816(acc[t], ah0, ah1, ah2, ah3, bf.z, bf.w);
                    mma16816(acc[t], al0, al1, al2, al3, bf.x, bf.y);
                }
            }

#pragma unroll
            for (int row = 0; row < 2; ++row) {
                float q0 = 0.f, q1 = 0.f, q2 = 0.f;
#pragma unroll
                for (int t = 0; t < 4; ++t) {
#pragma unroll
                    for (int e = 0; e < 2; ++e) {
                        uint4 c = sE[t][e][lane];
                        float h = acc[t][row * 2 + e] + __uint_as_float(c.x);
                        float act = __fdividef(h, 1.0f + __expf(-h));
                        q0 = fmaf(act, __uint_as_float(c.y), q0);
                        q1 = fmaf(act, __uint_as_float(c.z), q1);
                        q2 = fmaf(act, __uint_as_float(c.w), q2);
                    }
                }
                q0 += __shfl_xor_sync(0xffffffffu, q0, 1);
                q0 += __shfl_xor_sync(0xffffffffu, q0, 2);
                q1 += __shfl_xor_sync(0xffffffffu, q1, 1);
                q1 += __shfl_xor_sync(0xffffffffu, q1, 2);
                q2 += __shfl_xor_sync(0xffffffffu, q2, 1);
                q2 += __shfl_xor_sync(0xffffffffu, q2, 2);

                const int idx = ti * 16 + g + 8 * row;
                if (tig == 0 && idx < cnt) {
                    if (fast) {
                        swp[idx * 3 + 0] = q0 + bb0;
                        swp[idx * 3 + 1] = q1 + bb1;
                        swp[idx * 3 + 2] = q2 + bb2;
                    } else {
                        size_t o = (size_t)(s0 + idx) * H_DIM;
                        g_scores[o + 0] = q0 + bb0;
                        g_scores[o + 1] = q1 + bb1;
                        g_scores[o + 2] = q2 + bb2;
                    }
                }
            }
        }
        __syncwarp();

        float m0 = -3.4e38f, m1 = -3.4e38f, m2 = -3.4e38f;
        float r0v, r1v, r2v;
        ull acc0 = 0ull, acc1 = 0ull, acc2 = 0ull;

        if (fast) {
            // =========== Phase B: softmax over smem scores ===========
#pragma unroll
            for (int q = 0; q < 4; ++q) {
                int a = lane + 32 * q;
                if (a < cnt) {
                    m0 = fmaxf(m0, swp[a * 3 + 0]);
                    m1 = fmaxf(m1, swp[a * 3 + 1]);
                    m2 = fmaxf(m2, swp[a * 3 + 2]);
                }
            }
#pragma unroll
            for (int off = 16; off; off >>= 1) {
                m0 = fmaxf(m0, __shfl_xor_sync(0xffffffffu, m0, off));
                m1 = fmaxf(m1, __shfl_xor_sync(0xffffffffu, m1, off));
                m2 = fmaxf(m2, __shfl_xor_sync(0xffffffffu, m2, off));
            }
            float e0 = 0.f, e1 = 0.f, e2 = 0.f;
            float ex[4][3];
#pragma unroll
            for (int q = 0; q < 4; ++q) {
                int a = lane + 32 * q;
                if (a < cnt) {
                    ex[q][0] = __expf(swp[a * 3 + 0] - m0); e0 += ex[q][0];
                    ex[q][1] = __expf(swp[a * 3 + 1] - m1); e1 += ex[q][1];
                    ex[q][2] = __expf(swp[a * 3 + 2] - m2); e2 += ex[q][2];
                }
            }
#pragma unroll
            for (int off = 16; off; off >>= 1) {
                e0 += __shfl_xor_sync(0xffffffffu, e0, off);
                e1 += __shfl_xor_sync(0xffffffffu, e1, off);
                e2 += __shfl_xor_sync(0xffffffffu, e2, off);
            }
            r0v = 1.0f / e0; r1v = 1.0f / e1; r2v = 1.0f / e2;
            __syncwarp();
#pragma unroll
            for (int q = 0; q < 4; ++q) {
                int a = lane + 32 * q;
                if (a < cnt) {
                    swp[a * 3 + 0] = ex[q][0] * r0v;
                    swp[a * 3 + 1] = ex[q][1] * r1v;
                    swp[a * 3 + 2] = ex[q][2] * r2v;
                }
            }
            __syncwarp();

            // =========== Phase C: pooling (X rows L1/L2-hot) ===========
#pragma unroll 4
            for (int a = 0; a < cnt; ++a) {
                float2 xv = X2[(size_t)(s0 + a) * (D_DIM / 2) + lane];
                ull xx = *reinterpret_cast<ull*>(&xv);
                acc0 = fma2(xx, pack2(swp[a * 3 + 0]), acc0);
                acc1 = fma2(xx, pack2(swp[a * 3 + 1]), acc1);
                acc2 = fma2(xx, pack2(swp[a * 3 + 2]), acc2);
            }
        } else {
            // =========== rare big-segment path via g_scores ===========
            for (int n = s0 + lane; n < s1; n += 32) {
                size_t o = (size_t)n * H_DIM;
                m0 = fmaxf(m0, g_scores[o + 0]);
                m1 = fmaxf(m1, g_scores[o + 1]);
                m2 = fmaxf(m2, g_scores[o + 2]);
            }
#pragma unroll
            for (int off = 16; off; off >>= 1) {
                m0 = fmaxf(m0, __shfl_xor_sync(0xffffffffu, m0, off));
                m1 = fmaxf(m1, __shfl_xor_sync(0xffffffffu, m1, off));
                m2 = fmaxf(m2, __shfl_xor_sync(0xffffffffu, m2, off));
            }
            float e0 = 0.f, e1 = 0.f, e2 = 0.f;
            for (int n = s0 + lane; n < s1; n += 32) {
                size_t o = (size_t)n * H_DIM;
                e0 += __expf(g_scores[o + 0] - m0);
                e1 += __expf(g_scores[o + 1] - m1);
                e2 += __expf(g_scores[o + 2] - m2);
            }
#pragma unroll
            for (int off = 16; off; off >>= 1) {
                e0 += __shfl_xor_sync(0xffffffffu, e0, off);
                e1 += __shfl_xor_sync(0xffffffffu, e1, off);
                e2 += __shfl_xor_sync(0xffffffffu, e2, off);
            }
            r0v = 1.0f / e0; r1v = 1.0f / e1; r2v = 1.0f / e2;

            for (int base = 0; base < cnt; base += SEG_CAP) {
                int c = min(SEG_CAP, cnt - base);
#pragma unroll
                for (int q = 0; q < 4; ++q) {
                    int a = lane + 32 * q;
                    if (a < c) {
                        size_t o = (size_t)(s0 + base + a) * H_DIM;
                        swp[a * 3 + 0] = __expf(g_scores[o + 0] - m0) * r0v;
                        swp[a * 3 + 1] = __expf(g_scores[o + 1] - m1) * r1v;
                        swp[a * 3 + 2] = __expf(g_scores[o + 2] - m2) * r2v;
                    }
                }
                __syncwarp();
#pragma unroll 4
                for (int a = 0; a < c; ++a) {
                    float2 xv = X2[(size_t)(s0 + base + a) * (D_DIM / 2) + lane];
                    ull xx = *reinterpret_cast<ull*>(&xv);
                    acc0 = fma2(xx, pack2(swp[a * 3 + 0]), acc0);
                    acc1 = fma2(xx, pack2(swp[a * 3 + 1]), acc1);
                    acc2 = fma2(xx, pack2(swp[a * 3 + 2]), acc2);
                }
                __syncwarp();
            }
        }

        // ---- write out: lane owns d = 2*lane, 2*lane+1 ; layout [g][d][h] ----
        float v00, v01, v10, v11, v20, v21;
        unpack2(acc0, v00, v01);
        unpack2(acc1, v10, v11);
        unpack2(acc2, v20, v21);
        float* po = outg + lane * 6;
        po[0] = v00; po[1] = v10; po[2] = v20;
        po[3] = v01; po[4] = v11; po[5] = v21;
    }
}

// ---------------------------------------------------------------------------
extern "C" void kernel_launch(void* const* d_in, const int* in_sizes, int n_in,
                              void* d_out, int out_size)
{
    const float* X     = (const float*)d_in[0];
    const float* w1    = (const float*)d_in[1];
    const float* b1    = (const float*)d_in[2];
    const float* w2    = (const float*)d_in[3];
    const float* b2    = (const float*)d_in[4];
    const int*   owner = (const int*)  d_in[5];

    const int N = in_sizes[5];
    const int G = out_size / (D_DIM * H_DIM);

    k_bounds<<<(N + 255) / 256, 256>>>(owner, N, G);
    k_fused<<<888, 128>>>(X, w1, b1, w2, b2, (float*)d_out, N, G);
}

// round 10
// speedup vs baseline: 1.3554x; 1.0488x over previous
#include <cuda_runtime.h>
#include <cuda_bf16.h>
#include <cstdint>

// Problem shape (fixed by dataset): N=2,000,000 atoms, D=64, HID=32, H=3, G=50,000
#define D_DIM   64
#define HID_DIM 32
#define H_DIM   3

#define MAX_N 2000000
#define MAX_G 50000
#define SEG_CAP 128

typedef unsigned long long ull;

// Scratch (device globals)
__device__ float g_scores[(size_t)MAX_N * H_DIM];   // big-segment fallback only
__device__ int   g_segstart[MAX_G + 1];

// ---------------- packed fp32x2 helpers ----------------
__device__ __forceinline__ ull pack2(float v) {
    ull r; asm("mov.b64 %0, {%1, %1};" : "=l"(r) : "f"(v)); return r;
}
__device__ __forceinline__ ull fma2(ull a, ull b, ull c) {
    ull d; asm("fma.rn.f32x2 %0, %1, %2, %3;" : "=l"(d) : "l"(a), "l"(b), "l"(c)); return d;
}
__device__ __forceinline__ void unpack2(ull v, float& lo, float& hi) {
    asm("mov.b64 {%0, %1}, %2;" : "=f"(lo), "=f"(hi) : "l"(v));
}

// ---------------- bf16 helpers ----------------
__device__ __forceinline__ uint32_t pk2bf(float a, float b) {
    __nv_bfloat162 h = __floats2bfloat162_rn(a, b);
    return *reinterpret_cast<uint32_t*>(&h);
}
__device__ __forceinline__ float bfhi(float x) {
    return __bfloat162float(__float2bfloat16_rn(x));
}
// hi-part via truncation: one PRMT packs the top 16 bits of (a,b) -> bf16x2
__device__ __forceinline__ uint32_t pkhi_trunc(float a, float b) {
    uint32_t r;
    asm("prmt.b32 %0, %1, %2, 0x7632;"
        : "=r"(r) : "r"(__float_as_uint(a)), "r"(__float_as_uint(b)));
    return r;
}
__device__ __forceinline__ float trunchi(float x) {
    return __uint_as_float(__float_as_uint(x) & 0xffff0000u);
}

// warp-level tensor-core MMA (sm_80+ feature set; compiles for plain sm_103)
__device__ __forceinline__ void mma16816(float c[4],
    uint32_t a0, uint32_t a1, uint32_t a2, uint32_t a3,
    uint32_t b0, uint32_t b1)
{
    asm volatile(
        "mma.sync.aligned.m16n8k16.row.col.f32.bf16.bf16.f32 "
        "{%0,%1,%2,%3}, {%4,%5,%6,%7}, {%8,%9}, {%0,%1,%2,%3};"
        : "+f"(c[0]), "+f"(c[1]), "+f"(c[2]), "+f"(c[3])
        : "r"(a0), "r"(a1), "r"(a2), "r"(a3), "r"(b0), "r"(b1));
}

// ---------------------------------------------------------------------------
// Kernel 1: segment boundaries from sorted owner array.
// ---------------------------------------------------------------------------
__global__ void k_bounds(const int* __restrict__ owner, int N, int G)
{
    int i = blockIdx.x * blockDim.x + threadIdx.x;
    if (i >= N) return;
    int o = owner[i];
    if (i == 0) {
        for (int g = 0; g <= o; ++g) g_segstart[g] = 0;
    } else {
        int po = owner[i - 1];
        for (int g = po + 1; g <= o; ++g) g_segstart[g] = i;
    }
    if (i == N - 1) {
        for (int g = o + 1; g <= G; ++g) g_segstart[g] = N;
    }
}

// ---------------------------------------------------------------------------
// Kernel 2 (FUSED, low-reg, k-permuted, trunc-split): warp per segment.
// ---------------------------------------------------------------------------
__global__ __launch_bounds__(128, 7) void k_fused(
    const float* __restrict__ X,
    const float* __restrict__ w1, const float* __restrict__ b1,
    const float* __restrict__ w2, const float* __restrict__ b2,
    float* __restrict__ out, int N, int G)
{
    __shared__ uint4 sB[4][4][32];              // 8 KB  {bh0,bh1,bl0,bl1}
    __shared__ uint4 sE[4][2][32];              // 4 KB  {b1, w2_0, w2_1, w2_2}
    __shared__ float swbuf[4][SEG_CAP * H_DIM]; // 6 KB  raw scores
    __shared__ ull   sqbuf[4][SEG_CAP * H_DIM]; // 12 KB packed attn weights

    const int lane = threadIdx.x & 31;
    const int wid  = threadIdx.x >> 5;
    const int g    = lane >> 2;   // row group 0..7
    const int tig  = lane & 3;    // thread-in-group

    if (wid == 0) {
#pragma unroll
        for (int t = 0; t < 4; ++t) {
            const int col = g + 8 * t;
#pragma unroll
            for (int s = 0; s < 4; ++s) {
                // physical w1 rows under sigma: b0 <- {p0, p0+1}, b1 <- {p0+2, p0+3}
                const int p0 = 16 * s + 4 * tig;
                float w00 = __ldg(&w1[(p0 + 0) * HID_DIM + col]);
                float w01 = __ldg(&w1[(p0 + 1) * HID_DIM + col]);
                float w08 = __ldg(&w1[(p0 + 2) * HID_DIM + col]);
                float w09 = __ldg(&w1[(p0 + 3) * HID_DIM + col]);
                uint4 v;
                v.x = pk2bf(w00, w01);
                v.y = pk2bf(w08, w09);
                v.z = pk2bf(w00 - bfhi(w00), w01 - bfhi(w01));
                v.w = pk2bf(w08 - bfhi(w08), w09 - bfhi(w09));
                sB[t][s][lane] = v;
            }
#pragma unroll
            for (int e = 0; e < 2; ++e) {
                const int col2 = 8 * t + tig * 2 + e;
                uint4 v;
                v.x = __float_as_uint(__ldg(&b1[col2]));
                v.y = __float_as_uint(__ldg(&w2[col2 * H_DIM + 0]));
                v.z = __float_as_uint(__ldg(&w2[col2 * H_DIM + 1]));
                v.w = __float_as_uint(__ldg(&w2[col2 * H_DIM + 2]));
                sE[t][e][lane] = v;
            }
        }
    }
    __syncthreads();

    const float bb0 = __ldg(&b2[0]), bb1 = __ldg(&b2[1]), bb2 = __ldg(&b2[2]);

    float* swp = swbuf[wid];
    ull*   sqp = sqbuf[wid];
    const float2* X2 = reinterpret_cast<const float2*>(X);

    const int warp0 = blockIdx.x * 4 + wid;
    const int nwarp = gridDim.x * 4;

    for (int seg = warp0; seg < G; seg += nwarp) {
        const int s0  = g_segstart[seg];
        const int s1  = g_segstart[seg + 1];
        const int cnt = s1 - s0;
        float* outg = out + (size_t)seg * (D_DIM * H_DIM);

        if (cnt <= 0) {
            float2 z = make_float2(0.f, 0.f);
            float2* o2 = reinterpret_cast<float2*>(outg);
#pragma unroll
            for (int q = 0; q < 3; ++q) o2[lane + 32 * q] = z;
            continue;
        }

        // =========== Phase A: scores (mma.sync, k-permuted, trunc split) =====
        const bool fast = (cnt <= SEG_CAP);
        const int ntile = (cnt + 15) >> 4;
        for (int ti = 0; ti < ntile; ++ti) {
            float acc[4][4];
#pragma unroll
            for (int t = 0; t < 4; ++t) {
                acc[t][0] = 0.f; acc[t][1] = 0.f; acc[t][2] = 0.f; acc[t][3] = 0.f;
            }
            const int r0 = s0 + ti * 16 + g;
            const int r1 = r0 + 8;
            const float* x0 = X + (size_t)(r0 < s1 ? r0 : s1 - 1) * D_DIM;
            const float* x1 = X + (size_t)(r1 < s1 ? r1 : s1 - 1) * D_DIM;

#pragma unroll
            for (int s = 0; s < 4; ++s) {
                const int ks = 16 * s + 4 * tig;   // physical col base (sigma)
                float4 u0 = *reinterpret_cast<const float4*>(x0 + ks);
                float4 u1 = *reinterpret_cast<const float4*>(x1 + ks);

                // hi = truncated top-16 bits (1 PRMT per pair)
                uint32_t ah0 = pkhi_trunc(u0.x, u0.y);
                uint32_t ah1 = pkhi_trunc(u1.x, u1.y);
                uint32_t ah2 = pkhi_trunc(u0.z, u0.w);
                uint32_t ah3 = pkhi_trunc(u1.z, u1.w);
                // lo = x - trunc(x), rounded to bf16
                uint32_t al0 = pk2bf(u0.x - trunchi(u0.x), u0.y - trunchi(u0.y));
                uint32_t al1 = pk2bf(u1.x - trunchi(u1.x), u1.y - trunchi(u1.y));
                uint32_t al2 = pk2bf(u0.z - trunchi(u0.z), u0.w - trunchi(u0.w));
                uint32_t al3 = pk2bf(u1.z - trunchi(u1.z), u1.w - trunchi(u1.w));

#pragma unroll
                for (int t = 0; t < 4; ++t) {
                    uint4 bf = sB[t][s][lane];
                    mma16816(acc[t], ah0, ah1, ah2, ah3, bf.x, bf.y);
                    mma16816(acc[t], ah0, ah1, ah2, ah3, bf.z, bf.w);
                    mma16816(acc[t], al0, al1, al2, al3, bf.x, bf.y);
                }
            }

#pragma unroll
            for (int row = 0; row < 2; ++row) {
                float q0 = 0.f, q1 = 0.f, q2 = 0.f;
#pragma unroll
                for (int t = 0; t < 4; ++t) {
#pragma unroll
                    for (int e = 0; e < 2; ++e) {
                        uint4 c = sE[t][e][lane];
                        float h = acc[t][row * 2 + e] + __uint_as_float(c.x);
                        float act = __fdividef(h, 1.0f + __expf(-h));
                        q0 = fmaf(act, __uint_as_float(c.y), q0);
                        q1 = fmaf(act, __uint_as_float(c.z), q1);
                        q2 = fmaf(act, __uint_as_float(c.w), q2);
                    }
                }
                q0 += __shfl_xor_sync(0xffffffffu, q0, 1);
                q0 += __shfl_xor_sync(0xffffffffu, q0, 2);
                q1 += __shfl_xor_sync(0xffffffffu, q1, 1);
                q1 += __shfl_xor_sync(0xffffffffu, q1, 2);
                q2 += __shfl_xor_sync(0xffffffffu, q2, 1);
                q2 += __shfl_xor_sync(0xffffffffu, q2, 2);

                const int idx = ti * 16 + g + 8 * row;
                if (tig == 0 && idx < cnt) {
                    if (fast) {
                        swp[idx * 3 + 0] = q0 + bb0;
                        swp[idx * 3 + 1] = q1 + bb1;
                        swp[idx * 3 + 2] = q2 + bb2;
                    } else {
                        size_t o = (size_t)(s0 + idx) * H_DIM;
                        g_scores[o + 0] = q0 + bb0;
                        g_scores[o + 1] = q1 + bb1;
                        g_scores[o + 2] = q2 + bb2;
                    }
                }
            }
        }
        __syncwarp();

        float m0 = -3.4e38f, m1 = -3.4e38f, m2 = -3.4e38f;
        float r0v, r1v, r2v;
        ull acc0 = 0ull, acc1 = 0ull, acc2 = 0ull;

        if (fast) {
            // =========== Phase B: softmax -> packed attn in sqp ===========
#pragma unroll
            for (int q = 0; q < 4; ++q) {
                int a = lane + 32 * q;
                if (a < cnt) {
                    m0 = fmaxf(m0, swp[a * 3 + 0]);
                    m1 = fmaxf(m1, swp[a * 3 + 1]);
                    m2 = fmaxf(m2, swp[a * 3 + 2]);
                }
            }
#pragma unroll
            for (int off = 16; off; off >>= 1) {
                m0 = fmaxf(m0, __shfl_xor_sync(0xffffffffu, m0, off));
                m1 = fmaxf(m1, __shfl_xor_sync(0xffffffffu, m1, off));
                m2 = fmaxf(m2, __shfl_xor_sync(0xffffffffu, m2, off));
            }
            float e0 = 0.f, e1 = 0.f, e2 = 0.f;
            float ex[4][3];
#pragma unroll
            for (int q = 0; q < 4; ++q) {
                int a = lane + 32 * q;
                if (a < cnt) {
                    ex[q][0] = __expf(swp[a * 3 + 0] - m0); e0 += ex[q][0];
                    ex[q][1] = __expf(swp[a * 3 + 1] - m1); e1 += ex[q][1];
                    ex[q][2] = __expf(swp[a * 3 + 2] - m2); e2 += ex[q][2];
                }
            }
#pragma unroll
            for (int off = 16; off; off >>= 1) {
                e0 += __shfl_xor_sync(0xffffffffu, e0, off);
                e1 += __shfl_xor_sync(0xffffffffu, e1, off);
                e2 += __shfl_xor_sync(0xffffffffu, e2, off);
            }
            r0v = 1.0f / e0; r1v = 1.0f / e1; r2v = 1.0f / e2;
#pragma unroll
            for (int q = 0; q < 4; ++q) {
                int a = lane + 32 * q;
                if (a < cnt) {
                    sqp[a * 3 + 0] = pack2(ex[q][0] * r0v);
                    sqp[a * 3 + 1] = pack2(ex[q][1] * r1v);
                    sqp[a * 3 + 2] = pack2(ex[q][2] * r2v);
                }
            }
            __syncwarp();

            // =========== Phase C: pooling (packed weights, X L1/L2-hot) =====
#pragma unroll 4
            for (int a = 0; a < cnt; ++a) {
                float2 xv = X2[(size_t)(s0 + a) * (D_DIM / 2) + lane];
                ull xx = *reinterpret_cast<ull*>(&xv);
                acc0 = fma2(xx, sqp[a * 3 + 0], acc0);
                acc1 = fma2(xx, sqp[a * 3 + 1], acc1);
                acc2 = fma2(xx, sqp[a * 3 + 2], acc2);
            }
        } else {
            // =========== rare big-segment path via g_scores ===========
            for (int n = s0 + lane; n < s1; n += 32) {
                size_t o = (size_t)n * H_DIM;
                m0 = fmaxf(m0, g_scores[o + 0]);
                m1 = fmaxf(m1, g_scores[o + 1]);
                m2 = fmaxf(m2, g_scores[o + 2]);
            }
#pragma unroll
            for (int off = 16; off; off >>= 1) {
                m0 = fmaxf(m0, __shfl_xor_sync(0xffffffffu, m0, off));
                m1 = fmaxf(m1, __shfl_xor_sync(0xffffffffu, m1, off));
                m2 = fmaxf(m2, __shfl_xor_sync(0xffffffffu, m2, off));
            }
            float e0 = 0.f, e1 = 0.f, e2 = 0.f;
            for (int n = s0 + lane; n < s1; n += 32) {
                size_t o = (size_t)n * H_DIM;
                e0 += __expf(g_scores[o + 0] - m0);
                e1 += __expf(g_scores[o + 1] - m1);
                e2 += __expf(g_scores[o + 2] - m2);
            }
#pragma unroll
            for (int off = 16; off; off >>= 1) {
                e0 += __shfl_xor_sync(0xffffffffu, e0, off);
                e1 += __shfl_xor_sync(0xffffffffu, e1, off);
                e2 += __shfl_xor_sync(0xffffffffu, e2, off);
            }
            r0v = 1.0f / e0; r1v = 1.0f / e1; r2v = 1.0f / e2;

            for (int base = 0; base < cnt; base += SEG_CAP) {
                int c = min(SEG_CAP, cnt - base);
#pragma unroll
                for (int q = 0; q < 4; ++q) {
                    int a = lane + 32 * q;
                    if (a < c) {
                        size_t o = (size_t)(s0 + base + a) * H_DIM;
                        sqp[a * 3 + 0] = pack2(__expf(g_scores[o + 0] - m0) * r0v);
                        sqp[a * 3 + 1] = pack2(__expf(g_scores[o + 1] - m1) * r1v);
                        sqp[a * 3 + 2] = pack2(__expf(g_scores[o + 2] - m2) * r2v);
                    }
                }
                __syncwarp();
#pragma unroll 4
                for (int a = 0; a < c; ++a) {
                    float2 xv = X2[(size_t)(s0 + base + a) * (D_DIM / 2) + lane];
                    ull xx = *reinterpret_cast<ull*>(&xv);
                    acc0 = fma2(xx, sqp[a * 3 + 0], acc0);
                    acc1 = fma2(xx, sqp[a * 3 + 1], acc1);
                    acc2 = fma2(xx, sqp[a * 3 + 2], acc2);
                }
                __syncwarp();
            }
        }

        // ---- write out: lane owns d = 2*lane, 2*lane+1 ; layout [g][d][h] ----
        float v00, v01, v10, v11, v20, v21;
        unpack2(acc0, v00, v01);
        unpack2(acc1, v10, v11);
        unpack2(acc2, v20, v21);
        float* po = outg + lane * 6;
        po[0] = v00; po[1] = v10; po[2] = v20;
        po[3] = v01; po[4] = v11; po[5] = v21;
    }
}

// ---------------------------------------------------------------------------
extern "C" void kernel_launch(void* const* d_in, const int* in_sizes, int n_in,
                              void* d_out, int out_size)
{
    const float* X     = (const float*)d_in[0];
    const float* w1    = (const float*)d_in[1];
    const float* b1    = (const float*)d_in[2];
    const float* w2    = (const float*)d_in[3];
    const float* b2    = (const float*)d_in[4];
    const int*   owner = (const int*)  d_in[5];

    const int N = in_sizes[5];
    const int G = out_size / (D_DIM * H_DIM);

    k_bounds<<<(N + 255) / 256, 256>>>(owner, N, G);
    k_fused<<<1036, 128>>>(X, w1, b1, w2, b2, (float*)d_out, N, G);
}